// round 3
// baseline (speedup 1.0000x reference)
#include <cuda_runtime.h>
#include <math.h>

// Problem constants
#define DM   1024
#define DI   2048
#define DS   16
#define NB   4
#define LLEN 2048
#define NT   8192   // NB * LLEN tokens

// ---------------- scratch (device globals; no allocs allowed) ----------------
__device__ float g_xz[NT * (2 * DI)];   // [8192, 4096] in_proj output (xi | z)
__device__ float g_xi[NT * DI];         // conv+silu output
__device__ float g_delta[NT * DI];      // softplus(dt_proj)
__device__ float g_bc[NT * (2 * DS)];   // [8192, 32]  (B | C)
__device__ float g_fin[NT * DI];        // (y + xi*D) * silu(z)

// ---------------- fp32 NT GEMM: C[m,n] = sum_k A[m,k]*W[n,k] (+epilogue) -----
// BM=BN=128, BK=16, 256 threads, 8x8 per thread. M,N multiples of 128, K of 16.
// EPI: 0 = none, 1 = softplus(v + bias[n])
template<int EPI>
__global__ __launch_bounds__(256, 2) void gemm_nt(
    const float* __restrict__ A, const float* __restrict__ W,
    const float* __restrict__ bias, float* __restrict__ C,
    int M, int N, int K)
{
    constexpr int BM = 128, BN = 128, BK = 16;
    __shared__ __align__(16) float As[BK][BM];
    __shared__ __align__(16) float Ws[BK][BN];

    const int tid = threadIdx.x;
    const int tx  = tid & 15;       // n-dir micro tile
    const int ty  = tid >> 4;       // m-dir micro tile
    const int bm  = blockIdx.y * BM;
    const int bn  = blockIdx.x * BN;

    // loader mapping: 128 rows, 4 float4-quads per row, 2 threads/row x 2 quads
    const int lr = tid >> 1;            // row in tile 0..127
    const int lq = (tid & 1) * 2;       // quad base 0 or 2
    const float* Ap = A + (bm + lr) * K + lq * 4;
    const float* Wp = W + (bn + lr) * K + lq * 4;

    float acc[8][8];
#pragma unroll
    for (int i = 0; i < 8; i++)
#pragma unroll
        for (int j = 0; j < 8; j++) acc[i][j] = 0.f;

    for (int k0 = 0; k0 < K; k0 += BK) {
        float4 av0 = *(const float4*)(Ap + k0);
        float4 av1 = *(const float4*)(Ap + k0 + 4);
        float4 wv0 = *(const float4*)(Wp + k0);
        float4 wv1 = *(const float4*)(Wp + k0 + 4);

        As[lq * 4 + 0][lr] = av0.x;  As[lq * 4 + 1][lr] = av0.y;
        As[lq * 4 + 2][lr] = av0.z;  As[lq * 4 + 3][lr] = av0.w;
        As[lq * 4 + 4][lr] = av1.x;  As[lq * 4 + 5][lr] = av1.y;
        As[lq * 4 + 6][lr] = av1.z;  As[lq * 4 + 7][lr] = av1.w;
        Ws[lq * 4 + 0][lr] = wv0.x;  Ws[lq * 4 + 1][lr] = wv0.y;
        Ws[lq * 4 + 2][lr] = wv0.z;  Ws[lq * 4 + 3][lr] = wv0.w;
        Ws[lq * 4 + 4][lr] = wv1.x;  Ws[lq * 4 + 5][lr] = wv1.y;
        Ws[lq * 4 + 6][lr] = wv1.z;  Ws[lq * 4 + 7][lr] = wv1.w;
        __syncthreads();

#pragma unroll
        for (int kk = 0; kk < BK; kk++) {
            float4 a0 = *(const float4*)&As[kk][ty * 8];
            float4 a1 = *(const float4*)&As[kk][ty * 8 + 4];
            float4 b0 = *(const float4*)&Ws[kk][tx * 8];
            float4 b1 = *(const float4*)&Ws[kk][tx * 8 + 4];
            float a[8] = {a0.x, a0.y, a0.z, a0.w, a1.x, a1.y, a1.z, a1.w};
            float b[8] = {b0.x, b0.y, b0.z, b0.w, b1.x, b1.y, b1.z, b1.w};
#pragma unroll
            for (int i = 0; i < 8; i++)
#pragma unroll
                for (int j = 0; j < 8; j++)
                    acc[i][j] = fmaf(a[i], b[j], acc[i][j]);
        }
        __syncthreads();
    }

#pragma unroll
    for (int i = 0; i < 8; i++) {
        int row = bm + ty * 8 + i;
        float out[8];
#pragma unroll
        for (int j = 0; j < 8; j++) {
            float v = acc[i][j];
            if (EPI == 1) {
                v += bias[bn + tx * 8 + j];
                v = (v > 20.f) ? v : log1pf(__expf(v));   // softplus
            }
            out[j] = v;
        }
        float4* Cp = (float4*)(C + row * N + bn + tx * 8);
        Cp[0] = make_float4(out[0], out[1], out[2], out[3]);
        Cp[1] = make_float4(out[4], out[5], out[6], out[7]);
    }
}

// ---------------- depthwise causal conv (taps=4) + SiLU ----------------------
__global__ void conv_silu_k(const float* __restrict__ xz,
                            const float4* __restrict__ cw,
                            const float* __restrict__ cb,
                            float* __restrict__ xi)
{
    int idx = blockIdx.x * blockDim.x + threadIdx.x;   // over NT*DI
    int c = idx & (DI - 1);
    int t = idx >> 11;          // token index (DI = 2048)
    int l = t & (LLEN - 1);
    const float* base = xz + (t - l) * (2 * DI) + c;   // (b, l=0, c)
    float4 w = cw[c];
    float wj[4] = {w.x, w.y, w.z, w.w};
    float acc = cb[c];
#pragma unroll
    for (int j = 0; j < 4; j++) {
        int ll = l - 3 + j;
        if (ll >= 0) acc = fmaf(wj[j], base[ll * (2 * DI)], acc);
    }
    xi[idx] = acc / (1.f + __expf(-acc));              // silu
}

// ---------------- x_proj GEMM (N=32): bc[t, 0..31] ---------------------------
// block = 8 tokens (8 warps); lane = output column n; SMEM-chunked weights.
__global__ __launch_bounds__(256) void bc_k(const float* __restrict__ xi,
                                            const float* __restrict__ xw,
                                            float* __restrict__ bc)
{
    __shared__ float ws[32][257];
    __shared__ float xs[8][257];
    int tid = threadIdx.x, warp = tid >> 5, lane = tid & 31;
    int tok0 = blockIdx.x * 8;
    float acc = 0.f;
    for (int kc = 0; kc < DI; kc += 256) {
#pragma unroll
        for (int i = 0; i < 8; i++)                        // 32x256 weights
            ws[i * 2 + (tid >> 7)][tid & 127] = 0.f;       // (placeholder overwritten below)
        // weights: 32 rows x 256 cols, coalesced
#pragma unroll
        for (int i = 0; i < 32; i++)
            ws[i][tid] = (tid < 256) ? xw[i * DI + kc + tid] : 0.f;
        // activations: 8 tokens x 256 cols
#pragma unroll
        for (int i = 0; i < 8; i++)
            xs[i][tid] = xi[(tok0 + i) * DI + kc + tid];
        __syncthreads();
#pragma unroll 8
        for (int k = 0; k < 256; k++)
            acc = fmaf(xs[warp][k], ws[lane][k], acc);
        __syncthreads();
    }
    bc[(tok0 + warp) * (2 * DS) + lane] = acc;
}

// ---------------- selective scan + fused output gating -----------------------
// thread = (b, d, s): 16-lane state groups, xor-shuffle reduce over states.
__global__ __launch_bounds__(256) void scan_k(
    const float* __restrict__ delta, const float* __restrict__ bc,
    const float* __restrict__ xi,    const float* __restrict__ xz,
    const float* __restrict__ A_log, const float* __restrict__ Dp,
    float* __restrict__ fin)
{
    int g = blockIdx.x * 16 + (threadIdx.x >> 4);   // channel group (b,d)
    int s = threadIdx.x & 15;
    int b = g >> 11;
    int d = g & (DI - 1);

    float As = -expf(A_log[d * DS + s]);
    float Dd = Dp[d];

    int base_d  = (b * LLEN) * DI + d;
    int base_bc = (b * LLEN) * (2 * DS);
    int base_z  = (b * LLEN) * (2 * DI) + DI + d;

    float h = 0.f;
    for (int l = 0; l < LLEN; l++) {
        float dl = delta[base_d];
        float xv = xi[base_d];
        float Bt = bc[base_bc + s];
        float Ct = bc[base_bc + DS + s];
        float ab = __expf(dl * As);
        h = fmaf(ab, h, dl * Bt * xv);
        float y = h * Ct;
        y += __shfl_xor_sync(0xffffffffu, y, 1);
        y += __shfl_xor_sync(0xffffffffu, y, 2);
        y += __shfl_xor_sync(0xffffffffu, y, 4);
        y += __shfl_xor_sync(0xffffffffu, y, 8);
        if (s == 0) {
            float zv  = xz[base_z];
            float sig = 1.f / (1.f + __expf(-zv));
            fin[base_d] = (y + xv * Dd) * (zv * sig);
        }
        base_d  += DI;
        base_bc += 2 * DS;
        base_z  += 2 * DI;
    }
}

// ---------------- launch ------------------------------------------------------
extern "C" void kernel_launch(void* const* d_in, const int* in_sizes, int n_in,
                              void* d_out, int out_size)
{
    const float* x         = (const float*)d_in[0];
    const float* in_proj_w = (const float*)d_in[1];
    const float* conv_w    = (const float*)d_in[2];
    const float* conv_b    = (const float*)d_in[3];
    const float* x_proj_w  = (const float*)d_in[4];
    const float* dt_proj_w = (const float*)d_in[5];
    const float* dt_proj_b = (const float*)d_in[6];
    const float* A_log     = (const float*)d_in[7];
    const float* Dvec      = (const float*)d_in[8];
    const float* out_proj_w= (const float*)d_in[9];

    float *xz, *xi, *delta, *bcv, *fin;
    cudaGetSymbolAddress((void**)&xz,    g_xz);
    cudaGetSymbolAddress((void**)&xi,    g_xi);
    cudaGetSymbolAddress((void**)&delta, g_delta);
    cudaGetSymbolAddress((void**)&bcv,   g_bc);
    cudaGetSymbolAddress((void**)&fin,   g_fin);

    // 1) in_proj: [8192,1024] @ [4096,1024]^T -> xz [8192,4096]
    gemm_nt<0><<<dim3((2 * DI) / 128, NT / 128), 256>>>(
        x, in_proj_w, nullptr, xz, NT, 2 * DI, DM);

    // 2) causal depthwise conv + silu -> xi [8192,2048]
    conv_silu_k<<<(NT * DI) / 256, 256>>>(
        xz, (const float4*)conv_w, conv_b, xi);

    // 3) dt_proj + bias + softplus -> delta [8192,2048]
    gemm_nt<1><<<dim3(DI / 128, NT / 128), 256>>>(
        xi, dt_proj_w, dt_proj_b, delta, NT, DI, DI);

    // 4) x_proj -> bc [8192,32]
    bc_k<<<NT / 8, 256>>>(xi, x_proj_w, bcv);

    // 5) selective scan + (y + xi*D) * silu(z) -> fin [8192,2048]
    scan_k<<<(NB * DI) / 16, 256>>>(delta, bcv, xi, xz, A_log, Dvec, fin);

    // 6) out_proj: [8192,2048] @ [1024,2048]^T -> out [8192,1024]
    gemm_nt<0><<<dim3(DM / 128, NT / 128), 256>>>(
        fin, out_proj_w, nullptr, (float*)d_out, NT, DM, DI);
}

// round 9
// speedup vs baseline: 1.5814x; 1.5814x over previous
#include <cuda_runtime.h>
#include <cuda_fp16.h>
#include <math.h>
#include <stdint.h>

// Problem constants
#define DM   1024
#define DI   2048
#define DS   16
#define NB   4
#define LLEN 2048
#define NT   8192   // NB * LLEN tokens

// ---------------- scratch (device globals; no allocs allowed) ----------------
__device__ float g_xz[NT * (2 * DI)];      // in_proj output (xi | z)
__device__ float g_xi[NT * DI];            // conv+silu output
__device__ float g_delta[NT * DI];         // softplus(dt_proj)
__device__ float g_bc[NT * (2 * DS)];      // (B | C)
__device__ float g_fin[NT * DI];           // (y + xi*D) * silu(z)
__device__ __half g_ahi[NT * DI];          // activation split hi
__device__ __half g_alo[NT * DI];          // activation split lo
__device__ __half g_whi[4096 * 1024];      // weight split hi (max 4M elems)
__device__ __half g_wlo[4096 * 1024];      // weight split lo

// ============================ PTX helpers (baseline ISA only) ================
__device__ __forceinline__ uint32_t smem_u32(const void* p) {
    uint32_t a;
    asm("{ .reg .u64 t; cvta.to.shared.u64 t, %1; cvt.u32.u64 %0, t; }"
        : "=r"(a) : "l"(p));
    return a;
}
__device__ __forceinline__ void ldsm_x4(uint32_t* r, uint32_t addr) {
    asm volatile("ldmatrix.sync.aligned.m8n8.x4.shared.b16 {%0,%1,%2,%3}, [%4];"
                 : "=r"(r[0]), "=r"(r[1]), "=r"(r[2]), "=r"(r[3]) : "r"(addr));
}
__device__ __forceinline__ void mma16816(float* c, const uint32_t* a, const uint32_t* b) {
    asm volatile("mma.sync.aligned.m16n8k16.row.col.f32.f16.f16.f32 "
                 "{%0,%1,%2,%3}, {%4,%5,%6,%7}, {%8,%9}, {%0,%1,%2,%3};"
                 : "+f"(c[0]), "+f"(c[1]), "+f"(c[2]), "+f"(c[3])
                 : "r"(a[0]), "r"(a[1]), "r"(a[2]), "r"(a[3]), "r"(b[0]), "r"(b[1]));
}
#define CP_ASYNC16(dst, src) \
    asm volatile("cp.async.cg.shared.global [%0], [%1], 16;" :: "r"(dst), "l"(src))
#define CP_COMMIT() asm volatile("cp.async.commit_group;" ::: "memory")
#define CP_WAIT1()  asm volatile("cp.async.wait_group 1;" ::: "memory")

// ==================== fp16 split conversion (fp32 -> hi + lo) ================
__global__ __launch_bounds__(256) void split_k(const float4* __restrict__ in,
                                               __half* __restrict__ hi,
                                               __half* __restrict__ lo,
                                               int n4)
{
    int i = blockIdx.x * 256 + threadIdx.x;
    if (i >= n4) return;
    float4 v = in[i];
    float x[4] = {v.x, v.y, v.z, v.w};
    __half h[4], l[4];
#pragma unroll
    for (int j = 0; j < 4; j++) {
        h[j] = __float2half_rn(x[j]);
        l[j] = __float2half_rn(x[j] - __half2float(h[j]));
    }
    *(uint2*)(hi + 4 * i) = *(uint2*)h;
    *(uint2*)(lo + 4 * i) = *(uint2*)l;
}

// ==================== split-fp16 HMMA NT GEMM ================================
// C[m,n] = sum_k A[m,k]*W[n,k]; fp16 hi/lo pairs, fp32 accum.
//   D = AH*WH + AH*WL + AL*WH   (drops AL*WL ~ 2^-22 relative)
// Tile 128x128, BK=64, 3-stage cp.async pipeline, 8 warps (2m x 4n),
// warp tile 64x32 in m16n8k16 HMMAs. EPI: 0=none, 1=softplus(v+bias[n]).
// SMEM/stage: [Ahi|Alo|Whi|Wlo] x 16KB = 64KB; rows 128B, chunk^(row&7) swizzle.
template<int EPI>
__global__ __launch_bounds__(256, 1) void hmma_gemm(
    const __half* __restrict__ Ahi, const __half* __restrict__ Alo,
    const __half* __restrict__ Whi, const __half* __restrict__ Wlo,
    const float* __restrict__ bias, float* __restrict__ C,
    int N, int K)
{
    extern __shared__ char smem[];
    const uint32_t sb = smem_u32(smem);
    const int tid  = threadIdx.x;
    const int warp = tid >> 5, lane = tid & 31;
    const int wm = warp >> 2, wn = warp & 3;     // 2 x 4 warp grid
    const int bm = blockIdx.y * 128, bn = blockIdx.x * 128;
    const int iters = K >> 6;

    // ---- loader mapping: 4 tensors x 4 chunks(16B) per thread per stage ----
    const __half* bases[4] = {Ahi, Alo, Whi, Wlo};
    uint32_t s_dst[4][4];
    const __half* g_src[4][4];
#pragma unroll
    for (int i = 0; i < 4; i++) {
        int cid = tid * 4 + i;                  // 0..1023
        int row = cid >> 3, c = cid & 7;
        uint32_t soff = (uint32_t)row * 128 + ((uint32_t)(c ^ (row & 7)) << 4);
#pragma unroll
        for (int t = 0; t < 4; t++) {
            int rg = ((t < 2) ? bm : bn) + row;
            g_src[t][i] = bases[t] + (size_t)rg * K + c * 8;
            s_dst[t][i] = sb + t * 16384 + soff;
        }
    }

    // ---- ldmatrix lane address components ----
    const int arow = wm * 64 + (lane & 7) + ((lane >> 3) & 1) * 8;  // + mt*16
    const int ach  = lane >> 4;                                     // chunk half
    const int brow = wn * 32 + (lane & 7) + ((lane >> 4) & 1) * 8;  // + np*16
    const int bch  = (lane >> 3) & 1;
    const int xr   = lane & 7;                                      // row&7 for both

    float acc[4][4][4];
#pragma unroll
    for (int mt = 0; mt < 4; mt++)
#pragma unroll
        for (int nt = 0; nt < 4; nt++)
#pragma unroll
            for (int q = 0; q < 4; q++) acc[mt][nt][q] = 0.f;

    // prologue: stages 0,1
#pragma unroll 1
    for (int p = 0; p < 2; p++) {
        if (p < iters) {
            int k0 = p << 6;
            uint32_t so = (uint32_t)p * 65536;
#pragma unroll
            for (int t = 0; t < 4; t++)
#pragma unroll
                for (int i = 0; i < 4; i++)
                    CP_ASYNC16(s_dst[t][i] + so, g_src[t][i] + k0);
        }
        CP_COMMIT();
    }

    for (int it = 0; it < iters; it++) {
        CP_WAIT1();
        __syncthreads();
        // issue next stage loads (overlap with compute below)
        if (it + 2 < iters) {
            int k0 = (it + 2) << 6;
            uint32_t so = (uint32_t)((it + 2) % 3) * 65536;
#pragma unroll
            for (int t = 0; t < 4; t++)
#pragma unroll
                for (int i = 0; i < 4; i++)
                    CP_ASYNC16(s_dst[t][i] + so, g_src[t][i] + k0);
        }
        CP_COMMIT();

        const uint32_t so = (uint32_t)(it % 3) * 65536;
#pragma unroll
        for (int ks = 0; ks < 4; ks++) {
            uint32_t ah[4][4], al[4][4], bh[2][4], bl[2][4];
#pragma unroll
            for (int mt = 0; mt < 4; mt++) {
                uint32_t off = so + (uint32_t)(arow + mt * 16) * 128
                             + ((uint32_t)(((ks << 1) + ach) ^ xr) << 4);
                ldsm_x4(ah[mt], sb + off);
                ldsm_x4(al[mt], sb + 16384 + off);
            }
#pragma unroll
            for (int np = 0; np < 2; np++) {
                uint32_t off = so + (uint32_t)(brow + np * 16) * 128
                             + ((uint32_t)(((ks << 1) + bch) ^ xr) << 4);
                ldsm_x4(bh[np], sb + 32768 + off);
                ldsm_x4(bl[np], sb + 49152 + off);
            }
#pragma unroll
            for (int mt = 0; mt < 4; mt++)
#pragma unroll
                for (int np = 0; np < 2; np++)
#pragma unroll
                    for (int t2 = 0; t2 < 2; t2++) {
                        int nt = np * 2 + t2;
                        mma16816(acc[mt][nt], ah[mt], &bh[np][t2 * 2]);
                        mma16816(acc[mt][nt], ah[mt], &bl[np][t2 * 2]);
                        mma16816(acc[mt][nt], al[mt], &bh[np][t2 * 2]);
                    }
        }
    }

    // ---- epilogue: fragment -> global (optionally bias + softplus) ----
    const int r0   = bm + wm * 64 + (lane >> 2);
    const int col0 = bn + wn * 32 + (lane & 3) * 2;
#pragma unroll
    for (int mt = 0; mt < 4; mt++) {
#pragma unroll
        for (int nt = 0; nt < 4; nt++) {
            int row = r0 + mt * 16;
            int col = col0 + nt * 8;
            float v[4] = {acc[mt][nt][0], acc[mt][nt][1],
                          acc[mt][nt][2], acc[mt][nt][3]};
            if (EPI == 1) {
                float b0 = bias[col], b1 = bias[col + 1];
                v[0] += b0; v[1] += b1; v[2] += b0; v[3] += b1;
#pragma unroll
                for (int q = 0; q < 4; q++)
                    v[q] = (v[q] > 20.f) ? v[q] : log1pf(__expf(v[q]));
            }
            *(float2*)(C + (size_t)row * N + col)       = make_float2(v[0], v[1]);
            *(float2*)(C + (size_t)(row + 8) * N + col) = make_float2(v[2], v[3]);
        }
    }
}

// ---------------- depthwise causal conv (taps=4) + SiLU ----------------------
__global__ void conv_silu_k(const float* __restrict__ xz,
                            const float4* __restrict__ cw,
                            const float* __restrict__ cb,
                            float* __restrict__ xi)
{
    int idx = blockIdx.x * blockDim.x + threadIdx.x;   // over NT*DI
    int c = idx & (DI - 1);
    int t = idx >> 11;
    int l = t & (LLEN - 1);
    const float* base = xz + (t - l) * (2 * DI) + c;
    float4 w = cw[c];
    float wj[4] = {w.x, w.y, w.z, w.w};
    float acc = cb[c];
#pragma unroll
    for (int j = 0; j < 4; j++) {
        int ll = l - 3 + j;
        if (ll >= 0) acc = fmaf(wj[j], base[ll * (2 * DI)], acc);
    }
    xi[idx] = acc / (1.f + __expf(-acc));
}

// ---------------- x_proj GEMM (N=32): bc[t, 0..31] ---------------------------
__global__ __launch_bounds__(256) void bc_k(const float* __restrict__ xi,
                                            const float* __restrict__ xw,
                                            float* __restrict__ bc)
{
    __shared__ float ws[32][257];
    __shared__ float xs[8][257];
    int tid = threadIdx.x, warp = tid >> 5, lane = tid & 31;
    int tok0 = blockIdx.x * 8;
    float acc = 0.f;
    for (int kc = 0; kc < DI; kc += 256) {
#pragma unroll
        for (int i = 0; i < 32; i++)
            ws[i][tid] = xw[i * DI + kc + tid];
#pragma unroll
        for (int i = 0; i < 8; i++)
            xs[i][tid] = xi[(tok0 + i) * DI + kc + tid];
        __syncthreads();
#pragma unroll 8
        for (int k = 0; k < 256; k++)
            acc = fmaf(xs[warp][k], ws[lane][k], acc);
        __syncthreads();
    }
    bc[(tok0 + warp) * (2 * DS) + lane] = acc;
}

// ---------------- selective scan + fused output gating -----------------------
__global__ __launch_bounds__(256) void scan_k(
    const float* __restrict__ delta, const float* __restrict__ bc,
    const float* __restrict__ xi,    const float* __restrict__ xz,
    const float* __restrict__ A_log, const float* __restrict__ Dp,
    float* __restrict__ fin)
{
    int g = blockIdx.x * 16 + (threadIdx.x >> 4);
    int s = threadIdx.x & 15;
    int b = g >> 11;
    int d = g & (DI - 1);

    float As = -expf(A_log[d * DS + s]);
    float Dd = Dp[d];

    int base_d  = (b * LLEN) * DI + d;
    int base_bc = (b * LLEN) * (2 * DS);
    int base_z  = (b * LLEN) * (2 * DI) + DI + d;

    float h = 0.f;
    for (int l = 0; l < LLEN; l++) {
        float dl = delta[base_d];
        float xv = xi[base_d];
        float Bt = bc[base_bc + s];
        float Ct = bc[base_bc + DS + s];
        float ab = __expf(dl * As);
        h = fmaf(ab, h, dl * Bt * xv);
        float y = h * Ct;
        y += __shfl_xor_sync(0xffffffffu, y, 1);
        y += __shfl_xor_sync(0xffffffffu, y, 2);
        y += __shfl_xor_sync(0xffffffffu, y, 4);
        y += __shfl_xor_sync(0xffffffffu, y, 8);
        if (s == 0) {
            float zv  = xz[base_z];
            float sig = 1.f / (1.f + __expf(-zv));
            fin[base_d] = (y + xv * Dd) * (zv * sig);
        }
        base_d  += DI;
        base_bc += 2 * DS;
        base_z  += 2 * DI;
    }
}

// ---------------- launch ------------------------------------------------------
extern "C" void kernel_launch(void* const* d_in, const int* in_sizes, int n_in,
                              void* d_out, int out_size)
{
    const float* x          = (const float*)d_in[0];
    const float* in_proj_w  = (const float*)d_in[1];
    const float* conv_w     = (const float*)d_in[2];
    const float* conv_b     = (const float*)d_in[3];
    const float* x_proj_w   = (const float*)d_in[4];
    const float* dt_proj_w  = (const float*)d_in[5];
    const float* dt_proj_b  = (const float*)d_in[6];
    const float* A_log      = (const float*)d_in[7];
    const float* Dvec       = (const float*)d_in[8];
    const float* out_proj_w = (const float*)d_in[9];

    float *xz, *xi, *delta, *bcv, *fin;
    __half *ahi, *alo, *whi, *wlo;
    cudaGetSymbolAddress((void**)&xz,    g_xz);
    cudaGetSymbolAddress((void**)&xi,    g_xi);
    cudaGetSymbolAddress((void**)&delta, g_delta);
    cudaGetSymbolAddress((void**)&bcv,   g_bc);
    cudaGetSymbolAddress((void**)&fin,   g_fin);
    cudaGetSymbolAddress((void**)&ahi,   g_ahi);
    cudaGetSymbolAddress((void**)&alo,   g_alo);
    cudaGetSymbolAddress((void**)&whi,   g_whi);
    cudaGetSymbolAddress((void**)&wlo,   g_wlo);

    const int SMEM_SZ = 3 * 4 * 16384;   // 192 KB: 3 stages x 4 x 16KB tiles
    cudaFuncSetAttribute(hmma_gemm<0>, cudaFuncAttributeMaxDynamicSharedMemorySize, SMEM_SZ);
    cudaFuncSetAttribute(hmma_gemm<1>, cudaFuncAttributeMaxDynamicSharedMemorySize, SMEM_SZ);

    // 1) in_proj: x[8192,1024] @ W[4096,1024]^T -> xz
    split_k<<<(NT * DM / 4 + 255) / 256, 256>>>((const float4*)x, ahi, alo, NT * DM / 4);
    split_k<<<(4096 * 1024 / 4 + 255) / 256, 256>>>((const float4*)in_proj_w, whi, wlo, 4096 * 1024 / 4);
    hmma_gemm<0><<<dim3(4096 / 128, NT / 128), 256, SMEM_SZ>>>(
        ahi, alo, whi, wlo, nullptr, xz, 4096, DM);

    // 2) causal depthwise conv + silu -> xi
    conv_silu_k<<<(NT * DI) / 256, 256>>>(xz, (const float4*)conv_w, conv_b, xi);

    // 3) dt_proj + bias + softplus -> delta
    split_k<<<(NT * DI / 4 + 255) / 256, 256>>>((const float4*)xi, ahi, alo, NT * DI / 4);
    split_k<<<(DI * DI / 4 + 255) / 256, 256>>>((const float4*)dt_proj_w, whi, wlo, DI * DI / 4);
    hmma_gemm<1><<<dim3(DI / 128, NT / 128), 256, SMEM_SZ>>>(
        ahi, alo, whi, wlo, dt_proj_b, delta, DI, DI);

    // 4) x_proj -> bc (fp32, small N)
    bc_k<<<NT / 8, 256>>>(xi, x_proj_w, bcv);

    // 5) selective scan + (y + xi*D) * silu(z) -> fin
    scan_k<<<(NB * DI) / 16, 256>>>(delta, bcv, xi, xz, A_log, Dvec, fin);

    // 6) out_proj: fin[8192,2048] @ W[1024,2048]^T -> out
    split_k<<<(NT * DI / 4 + 255) / 256, 256>>>((const float4*)fin, ahi, alo, NT * DI / 4);
    split_k<<<(DM * DI / 4 + 255) / 256, 256>>>((const float4*)out_proj_w, whi, wlo, DM * DI / 4);
    hmma_gemm<0><<<dim3(DM / 128, NT / 128), 256, SMEM_SZ>>>(
        ahi, alo, whi, wlo, nullptr, (float*)d_out, DM, DI);
}

// round 11
// speedup vs baseline: 1.7955x; 1.1354x over previous
#include <cuda_runtime.h>
#include <cuda_fp16.h>
#include <math.h>
#include <stdint.h>

// Problem constants
#define DM   1024
#define DI   2048
#define DS   16
#define NB   4
#define LLEN 2048
#define NT   8192   // NB * LLEN tokens

// ---------------- scratch (device globals; no allocs allowed) ----------------
// Packed hi/lo layout (per tensor, rows R, inner dim K):
//   tile (rt, kc) = 128 rows x 64 k, 16KB contiguous, pre-swizzled:
//   half_index = tile*8192 + (row&127)*64 + ((((k>>3) ^ row) & 7) << 3) + (k&7)
//   tile = (row>>7)*(K>>6) + (k>>6)
__device__ float g_xz[NT * (2 * DI)];      // in_proj output (xi | z)
__device__ float g_xi[NT * DI];            // conv+silu output (fp32, for bc/scan)
__device__ float g_delta[NT * DI];         // softplus(dt_proj)
__device__ float g_bc[NT * (2 * DS)];      // (B | C)
__device__ float g_fin[NT * DI];           // (y + xi*D) * silu(z)
__device__ __half g_ahi[NT * DI];          // packed activation hi
__device__ __half g_alo[NT * DI];          // packed activation lo
__device__ __half g_whi[4096 * 1024];      // packed weight hi
__device__ __half g_wlo[4096 * 1024];      // packed weight lo

// ============================ PTX helpers (sm_90 baseline ISA) ===============
__device__ __forceinline__ uint32_t smem_u32(const void* p) {
    uint32_t a;
    asm("{ .reg .u64 t; cvta.to.shared.u64 t, %1; cvt.u32.u64 %0, t; }"
        : "=r"(a) : "l"(p));
    return a;
}
__device__ __forceinline__ void ldsm_x4(uint32_t* r, uint32_t addr) {
    asm volatile("ldmatrix.sync.aligned.m8n8.x4.shared.b16 {%0,%1,%2,%3}, [%4];"
                 : "=r"(r[0]), "=r"(r[1]), "=r"(r[2]), "=r"(r[3]) : "r"(addr));
}
__device__ __forceinline__ void mma16816(float* c, const uint32_t* a, const uint32_t* b) {
    asm volatile("mma.sync.aligned.m16n8k16.row.col.f32.f16.f16.f32 "
                 "{%0,%1,%2,%3}, {%4,%5,%6,%7}, {%8,%9}, {%0,%1,%2,%3};"
                 : "+f"(c[0]), "+f"(c[1]), "+f"(c[2]), "+f"(c[3])
                 : "r"(a[0]), "r"(a[1]), "r"(a[2]), "r"(a[3]), "r"(b[0]), "r"(b[1]));
}
#define MBAR_INIT(addr, cnt) \
    asm volatile("mbarrier.init.shared.b64 [%0], %1;" :: "r"(addr), "r"(cnt) : "memory")
#define MBAR_EXPECT_TX(addr, bytes) \
    asm volatile("mbarrier.arrive.expect_tx.shared.b64 _, [%0], %1;" \
                 :: "r"(addr), "r"(bytes) : "memory")
#define MBAR_WAIT(addr, par) do {                                               \
    uint32_t _m = (addr), _p = (par), _d;                                       \
    asm volatile("{\n\t.reg .pred p;\n\t"                                       \
        "mbarrier.try_wait.parity.acquire.cta.shared::cta.b64 p, [%1], %2;\n\t" \
        "selp.b32 %0, 1, 0, p;\n\t}" : "=r"(_d) : "r"(_m), "r"(_p) : "memory"); \
    if (!_d) {                                                                  \
        asm volatile("{\n\t.reg .pred P1;\n\tWL_%=:\n\t"                        \
            "mbarrier.try_wait.parity.acquire.cta.shared::cta.b64 P1, [%0], %1, 0x989680;\n\t" \
            "@P1 bra.uni WD_%=;\n\tbra.uni WL_%=;\n\tWD_%=:\n\t}"               \
            :: "r"(_m), "r"(_p) : "memory");                                    \
    }                                                                           \
} while (0)
// 1D bulk TMA: global -> shared, completion via mbarrier tx-bytes
#define CP_BULK(dst, src, bytes, mbar) \
    asm volatile("cp.async.bulk.shared::cluster.global.mbarrier::complete_tx::bytes " \
                 "[%0], [%1], %2, [%3];" \
                 :: "r"(dst), "l"(src), "r"(bytes), "r"(mbar) : "memory")

// ==================== generic fp32 -> packed fp16 hi/lo ======================
// kshift = log2(K). Thread handles 4 consecutive k of one row (same 16B chunk half).
__global__ __launch_bounds__(256) void split_pack_k(
    const float4* __restrict__ in, __half* __restrict__ hi, __half* __restrict__ lo,
    int kshift, int n4)
{
    int i = blockIdx.x * 256 + threadIdx.x;
    if (i >= n4) return;
    int e   = i << 2;
    int row = e >> kshift;
    int k   = e & ((1 << kshift) - 1);
    float4 v = in[i];
    float x[4] = {v.x, v.y, v.z, v.w};
    __half h[4], l[4];
#pragma unroll
    for (int j = 0; j < 4; j++) {
        h[j] = __float2half_rn(x[j]);
        l[j] = __float2half_rn(x[j] - __half2float(h[j]));
    }
    int tile = (row >> 7) * (1 << (kshift - 6)) + (k >> 6);
    size_t idx = (size_t)tile * 8192 + (row & 127) * 64
               + ((((k >> 3) ^ row) & 7) << 3) + (k & 7);
    *(uint2*)(hi + idx) = *(uint2*)h;
    *(uint2*)(lo + idx) = *(uint2*)l;
}

// ==================== split-fp16 HMMA NT GEMM (bulk-TMA staged) ==============
// C[m,n] = sum_k A[m,k]*W[n,k];  D = AH*WH + AH*WL + AL*WH  (drops AL*WL)
// Sources are PACKED pre-swizzled tiles. Tile 128x128, BK=64, 3-stage TMA
// pipeline (4 bulk copies/stage issued by tid 0). 8 warps (2m x 4n),
// warp tile 64x32 m16n8k16. EPI: 0=none, 1=softplus(v+bias[n]).
template<int EPI>
__global__ __launch_bounds__(256, 1) void hmma_gemm(
    const __half* __restrict__ Ahi, const __half* __restrict__ Alo,
    const __half* __restrict__ Whi, const __half* __restrict__ Wlo,
    const float* __restrict__ bias, float* __restrict__ C,
    int N, int K)
{
    extern __shared__ __align__(128) char smem[];
    __shared__ __align__(8) uint64_t mbars[3];
    const uint32_t sb = smem_u32(smem);
    const int tid  = threadIdx.x;
    const int warp = tid >> 5, lane = tid & 31;
    const int wm = warp >> 2, wn = warp & 3;     // 2 x 4 warp grid
    const int bm = blockIdx.y * 128, bn = blockIdx.x * 128;
    const int iters = K >> 6;

    uint32_t mba[3];
#pragma unroll
    for (int s = 0; s < 3; s++) mba[s] = smem_u32(&mbars[s]);
    if (tid == 0) {
#pragma unroll
        for (int s = 0; s < 3; s++) MBAR_INIT(mba[s], 1);
    }
    __syncthreads();

    // packed tile bases (bytes): tile row index * (K/64) tiles, 16KB each
    const char* srcA_hi = (const char*)Ahi + (size_t)(bm >> 7) * iters * 16384;
    const char* srcA_lo = (const char*)Alo + (size_t)(bm >> 7) * iters * 16384;
    const char* srcW_hi = (const char*)Whi + (size_t)(bn >> 7) * iters * 16384;
    const char* srcW_lo = (const char*)Wlo + (size_t)(bn >> 7) * iters * 16384;

    // prologue: stages 0..2 <- iters 0..2
    if (tid == 0) {
#pragma unroll
        for (int s = 0; s < 3; s++) {
            MBAR_EXPECT_TX(mba[s], 65536u);
            uint32_t d = sb + (uint32_t)s * 65536u;
            size_t o = (size_t)s * 16384;
            CP_BULK(d,         srcA_hi + o, 16384u, mba[s]);
            CP_BULK(d + 16384, srcA_lo + o, 16384u, mba[s]);
            CP_BULK(d + 32768, srcW_hi + o, 16384u, mba[s]);
            CP_BULK(d + 49152, srcW_lo + o, 16384u, mba[s]);
        }
    }

    // ldmatrix lane address components
    const int arow = wm * 64 + (lane & 7) + ((lane >> 3) & 1) * 8;  // + mt*16
    const int ach  = lane >> 4;
    const int brow = wn * 32 + (lane & 7) + ((lane >> 4) & 1) * 8;  // + np*16
    const int bch  = (lane >> 3) & 1;
    const int xr   = lane & 7;

    float acc[4][4][4];
#pragma unroll
    for (int mt = 0; mt < 4; mt++)
#pragma unroll
        for (int nt = 0; nt < 4; nt++)
#pragma unroll
            for (int q = 0; q < 4; q++) acc[mt][nt][q] = 0.f;

    int ph0 = 0, ph1 = 0, ph2 = 0;
    for (int it = 0; it < iters; it++) {
        const int st = it % 3;
        if (st == 0)      { MBAR_WAIT(mba[0], ph0); ph0 ^= 1; }
        else if (st == 1) { MBAR_WAIT(mba[1], ph1); ph1 ^= 1; }
        else              { MBAR_WAIT(mba[2], ph2); ph2 ^= 1; }

        const uint32_t so = (uint32_t)st * 65536u;
#pragma unroll
        for (int ks = 0; ks < 4; ks++) {
            uint32_t ah[4][4], al[4][4], bh[2][4], bl[2][4];
#pragma unroll
            for (int mt = 0; mt < 4; mt++) {
                uint32_t off = so + (uint32_t)(arow + mt * 16) * 128
                             + ((uint32_t)(((ks << 1) + ach) ^ xr) << 4);
                ldsm_x4(ah[mt], sb + off);
                ldsm_x4(al[mt], sb + 16384 + off);
            }
#pragma unroll
            for (int np = 0; np < 2; np++) {
                uint32_t off = so + (uint32_t)(brow + np * 16) * 128
                             + ((uint32_t)(((ks << 1) + bch) ^ xr) << 4);
                ldsm_x4(bh[np], sb + 32768 + off);
                ldsm_x4(bl[np], sb + 49152 + off);
            }
#pragma unroll
            for (int mt = 0; mt < 4; mt++)
#pragma unroll
                for (int np = 0; np < 2; np++)
#pragma unroll
                    for (int t2 = 0; t2 < 2; t2++) {
                        int nt = np * 2 + t2;
                        mma16816(acc[mt][nt], ah[mt], &bh[np][t2 * 2]);
                        mma16816(acc[mt][nt], ah[mt], &bl[np][t2 * 2]);
                        mma16816(acc[mt][nt], al[mt], &bh[np][t2 * 2]);
                    }
        }
        __syncthreads();   // all warps done reading stage st
        if (tid == 0 && it + 3 < iters) {
            MBAR_EXPECT_TX(mba[st], 65536u);
            uint32_t d = sb + so;
            size_t o = (size_t)(it + 3) * 16384;
            CP_BULK(d,         srcA_hi + o, 16384u, mba[st]);
            CP_BULK(d + 16384, srcA_lo + o, 16384u, mba[st]);
            CP_BULK(d + 32768, srcW_hi + o, 16384u, mba[st]);
            CP_BULK(d + 49152, srcW_lo + o, 16384u, mba[st]);
        }
    }

    // ---- epilogue: fragment -> global (optionally bias + softplus) ----
    const int r0   = bm + wm * 64 + (lane >> 2);
    const int col0 = bn + wn * 32 + (lane & 3) * 2;
#pragma unroll
    for (int mt = 0; mt < 4; mt++) {
#pragma unroll
        for (int nt = 0; nt < 4; nt++) {
            int row = r0 + mt * 16;
            int col = col0 + nt * 8;
            float v[4] = {acc[mt][nt][0], acc[mt][nt][1],
                          acc[mt][nt][2], acc[mt][nt][3]};
            if (EPI == 1) {
                float b0 = bias[col], b1 = bias[col + 1];
                v[0] += b0; v[1] += b1; v[2] += b0; v[3] += b1;
#pragma unroll
                for (int q = 0; q < 4; q++)
                    v[q] = (v[q] > 20.f) ? v[q] : log1pf(__expf(v[q]));
            }
            *(float2*)(C + (size_t)row * N + col)       = make_float2(v[0], v[1]);
            *(float2*)(C + (size_t)(row + 8) * N + col) = make_float2(v[2], v[3]);
        }
    }
}

// ---------- depthwise causal conv (taps=4) + SiLU + fused hi/lo pack ---------
// 4 consecutive channels per thread; writes fp32 xi AND packed hi/lo (K=DI).
__global__ __launch_bounds__(256) void conv_silu_pack_k(
    const float* __restrict__ xz, const float4* __restrict__ cw,
    const float* __restrict__ cb, float* __restrict__ xi,
    __half* __restrict__ hi, __half* __restrict__ lo)
{
    int i = blockIdx.x * 256 + threadIdx.x;   // over NT*DI/4
    int e = i << 2;
    int c = e & (DI - 1);
    int t = e >> 11;
    int l = t & (LLEN - 1);
    const float* base = xz + (size_t)(t - l) * (2 * DI) + c;
    float4 w0 = cw[c], w1 = cw[c + 1], w2 = cw[c + 2], w3 = cw[c + 3];
    float4 bz = *(const float4*)(cb + c);
    float acc[4] = {bz.x, bz.y, bz.z, bz.w};
#pragma unroll
    for (int j = 0; j < 4; j++) {
        int ll = l - 3 + j;
        if (ll >= 0) {
            float4 v = *(const float4*)(base + (size_t)ll * (2 * DI));
            acc[0] = fmaf(((const float*)&w0)[j], v.x, acc[0]);
            acc[1] = fmaf(((const float*)&w1)[j], v.y, acc[1]);
            acc[2] = fmaf(((const float*)&w2)[j], v.z, acc[2]);
            acc[3] = fmaf(((const float*)&w3)[j], v.w, acc[3]);
        }
    }
    __half h[4], lw[4];
#pragma unroll
    for (int q = 0; q < 4; q++) {
        acc[q] = acc[q] / (1.f + __expf(-acc[q]));   // silu
        h[q]  = __float2half_rn(acc[q]);
        lw[q] = __float2half_rn(acc[q] - __half2float(h[q]));
    }
    *(float4*)(xi + e) = make_float4(acc[0], acc[1], acc[2], acc[3]);
    int tile = (t >> 7) * 32 + (c >> 6);
    size_t idx = (size_t)tile * 8192 + (t & 127) * 64
               + ((((c >> 3) ^ t) & 7) << 3) + (c & 7);
    *(uint2*)(hi + idx) = *(uint2*)h;
    *(uint2*)(lo + idx) = *(uint2*)lw;
}

// ---------------- x_proj GEMM (N=32): bc[t, 0..31] ---------------------------
__global__ __launch_bounds__(256) void bc_k(const float* __restrict__ xi,
                                            const float* __restrict__ xw,
                                            float* __restrict__ bc)
{
    __shared__ float ws[32][257];
    __shared__ float xs[8][257];
    int tid = threadIdx.x, warp = tid >> 5, lane = tid & 31;
    int tok0 = blockIdx.x * 8;
    float acc = 0.f;
    for (int kc = 0; kc < DI; kc += 256) {
#pragma unroll
        for (int i = 0; i < 32; i++)
            ws[i][tid] = xw[i * DI + kc + tid];
#pragma unroll
        for (int i = 0; i < 8; i++)
            xs[i][tid] = xi[(tok0 + i) * DI + kc + tid];
        __syncthreads();
#pragma unroll 8
        for (int k = 0; k < 256; k++)
            acc = fmaf(xs[warp][k], ws[lane][k], acc);
        __syncthreads();
    }
    bc[(tok0 + warp) * (2 * DS) + lane] = acc;
}

// ---------------- selective scan + fused output gating -----------------------
__global__ __launch_bounds__(256) void scan_k(
    const float* __restrict__ delta, const float* __restrict__ bc,
    const float* __restrict__ xi,    const float* __restrict__ xz,
    const float* __restrict__ A_log, const float* __restrict__ Dp,
    float* __restrict__ fin)
{
    int g = blockIdx.x * 16 + (threadIdx.x >> 4);
    int s = threadIdx.x & 15;
    int b = g >> 11;
    int d = g & (DI - 1);

    float As = -expf(A_log[d * DS + s]);
    float Dd = Dp[d];

    int base_d  = (b * LLEN) * DI + d;
    int base_bc = (b * LLEN) * (2 * DS);
    int base_z  = (b * LLEN) * (2 * DI) + DI + d;

    float h = 0.f;
    for (int l = 0; l < LLEN; l++) {
        float dl = delta[base_d];
        float xv = xi[base_d];
        float Bt = bc[base_bc + s];
        float Ct = bc[base_bc + DS + s];
        float ab = __expf(dl * As);
        h = fmaf(ab, h, dl * Bt * xv);
        float y = h * Ct;
        y += __shfl_xor_sync(0xffffffffu, y, 1);
        y += __shfl_xor_sync(0xffffffffu, y, 2);
        y += __shfl_xor_sync(0xffffffffu, y, 4);
        y += __shfl_xor_sync(0xffffffffu, y, 8);
        if (s == 0) {
            float zv  = xz[base_z];
            float sig = 1.f / (1.f + __expf(-zv));
            fin[base_d] = (y + xv * Dd) * (zv * sig);
        }
        base_d  += DI;
        base_bc += 2 * DS;
        base_z  += 2 * DI;
    }
}

// ---------------- launch ------------------------------------------------------
extern "C" void kernel_launch(void* const* d_in, const int* in_sizes, int n_in,
                              void* d_out, int out_size)
{
    const float* x          = (const float*)d_in[0];
    const float* in_proj_w  = (const float*)d_in[1];
    const float* conv_w     = (const float*)d_in[2];
    const float* conv_b     = (const float*)d_in[3];
    const float* x_proj_w   = (const float*)d_in[4];
    const float* dt_proj_w  = (const float*)d_in[5];
    const float* dt_proj_b  = (const float*)d_in[6];
    const float* A_log      = (const float*)d_in[7];
    const float* Dvec       = (const float*)d_in[8];
    const float* out_proj_w = (const float*)d_in[9];

    float *xz, *xi, *delta, *bcv, *fin;
    __half *ahi, *alo, *whi, *wlo;
    cudaGetSymbolAddress((void**)&xz,    g_xz);
    cudaGetSymbolAddress((void**)&xi,    g_xi);
    cudaGetSymbolAddress((void**)&delta, g_delta);
    cudaGetSymbolAddress((void**)&bcv,   g_bc);
    cudaGetSymbolAddress((void**)&fin,   g_fin);
    cudaGetSymbolAddress((void**)&ahi,   g_ahi);
    cudaGetSymbolAddress((void**)&alo,   g_alo);
    cudaGetSymbolAddress((void**)&whi,   g_whi);
    cudaGetSymbolAddress((void**)&wlo,   g_wlo);

    const int SMEM_SZ = 3 * 4 * 16384;   // 192 KB: 3 stages x 4 x 16KB tiles
    cudaFuncSetAttribute(hmma_gemm<0>, cudaFuncAttributeMaxDynamicSharedMemorySize, SMEM_SZ);
    cudaFuncSetAttribute(hmma_gemm<1>, cudaFuncAttributeMaxDynamicSharedMemorySize, SMEM_SZ);

    // 1) in_proj: x[8192,1024] @ W[4096,1024]^T -> xz
    split_pack_k<<<(NT * DM / 4 + 255) / 256, 256>>>((const float4*)x, ahi, alo, 10, NT * DM / 4);
    split_pack_k<<<(4096 * 1024 / 4 + 255) / 256, 256>>>((const float4*)in_proj_w, whi, wlo, 10, 4096 * 1024 / 4);
    hmma_gemm<0><<<dim3(4096 / 128, NT / 128), 256, SMEM_SZ>>>(
        ahi, alo, whi, wlo, nullptr, xz, 4096, DM);

    // 2) causal depthwise conv + silu -> xi (fp32) + packed hi/lo (for dt GEMM)
    conv_silu_pack_k<<<(NT * DI / 4) / 256, 256>>>(
        xz, (const float4*)conv_w, conv_b, xi, ahi, alo);

    // 3) dt_proj + bias + softplus -> delta
    split_pack_k<<<(DI * DI / 4 + 255) / 256, 256>>>((const float4*)dt_proj_w, whi, wlo, 11, DI * DI / 4);
    hmma_gemm<1><<<dim3(DI / 128, NT / 128), 256, SMEM_SZ>>>(
        ahi, alo, whi, wlo, dt_proj_b, delta, DI, DI);

    // 4) x_proj -> bc (fp32, small N)
    bc_k<<<NT / 8, 256>>>(xi, x_proj_w, bcv);

    // 5) selective scan + (y + xi*D) * silu(z) -> fin
    scan_k<<<(NB * DI) / 16, 256>>>(delta, bcv, xi, xz, A_log, Dvec, fin);

    // 6) out_proj: fin[8192,2048] @ W[1024,2048]^T -> out
    split_pack_k<<<(NT * DI / 4 + 255) / 256, 256>>>((const float4*)fin, ahi, alo, 11, NT * DI / 4);
    split_pack_k<<<(DM * DI / 4 + 255) / 256, 256>>>((const float4*)out_proj_w, whi, wlo, 11, DM * DI / 4);
    hmma_gemm<0><<<dim3(DM / 128, NT / 128), 256, SMEM_SZ>>>(
        ahi, alo, whi, wlo, nullptr, (float*)d_out, DM, DI);
}

// round 12
// speedup vs baseline: 1.8562x; 1.0338x over previous
#include <cuda_runtime.h>
#include <cuda_fp16.h>
#include <math.h>
#include <stdint.h>

// Problem constants
#define DM   1024
#define DI   2048
#define DS   16
#define NB   4
#define LLEN 2048
#define NT   8192   // NB * LLEN tokens

// ---------------- scratch (device globals; no allocs allowed) ----------------
// Packed hi/lo layout (per tensor, rows R, inner dim K, RT = rows/tile):
//   tile (rt, kc) = RT rows x 64 k, RT*128 bytes contiguous, pre-swizzled:
//   half_index = tile*(RT*64) + (row&(RT-1))*64 + ((((k>>3) ^ row) & 7) << 3) + (k&7)
//   tile = (row>>log2RT)*(K>>6) + (k>>6)
// Activations (A operand): RT=128 (16KB tiles). Weights (B operand): RT=64 (8KB tiles).
__device__ float g_xz[NT * (2 * DI)];      // in_proj output (xi | z)
__device__ float g_xi[NT * DI];            // conv+silu output (fp32, for bc/scan)
__device__ float g_delta[NT * DI];         // softplus(dt_proj)
__device__ float g_bc[NT * (2 * DS)];      // (B | C)
__device__ float g_fin[NT * DI];           // (y + xi*D) * silu(z)
__device__ __half g_ahi[NT * DI];          // packed activation hi
__device__ __half g_alo[NT * DI];          // packed activation lo
__device__ __half g_whi[4096 * 1024];      // packed weight hi
__device__ __half g_wlo[4096 * 1024];      // packed weight lo

// ============================ PTX helpers (sm_90 baseline ISA) ===============
__device__ __forceinline__ uint32_t smem_u32(const void* p) {
    uint32_t a;
    asm("{ .reg .u64 t; cvta.to.shared.u64 t, %1; cvt.u32.u64 %0, t; }"
        : "=r"(a) : "l"(p));
    return a;
}
__device__ __forceinline__ void ldsm_x4(uint32_t* r, uint32_t addr) {
    asm volatile("ldmatrix.sync.aligned.m8n8.x4.shared.b16 {%0,%1,%2,%3}, [%4];"
                 : "=r"(r[0]), "=r"(r[1]), "=r"(r[2]), "=r"(r[3]) : "r"(addr));
}
__device__ __forceinline__ void mma16816(float* c, const uint32_t* a, const uint32_t* b) {
    asm volatile("mma.sync.aligned.m16n8k16.row.col.f32.f16.f16.f32 "
                 "{%0,%1,%2,%3}, {%4,%5,%6,%7}, {%8,%9}, {%0,%1,%2,%3};"
                 : "+f"(c[0]), "+f"(c[1]), "+f"(c[2]), "+f"(c[3])
                 : "r"(a[0]), "r"(a[1]), "r"(a[2]), "r"(a[3]), "r"(b[0]), "r"(b[1]));
}
#define MBAR_INIT(addr, cnt) \
    asm volatile("mbarrier.init.shared.b64 [%0], %1;" :: "r"(addr), "r"(cnt) : "memory")
#define MBAR_EXPECT_TX(addr, bytes) \
    asm volatile("mbarrier.arrive.expect_tx.shared.b64 _, [%0], %1;" \
                 :: "r"(addr), "r"(bytes) : "memory")
#define MBAR_WAIT(addr, par) do {                                               \
    uint32_t _m = (addr), _p = (par), _d;                                       \
    asm volatile("{\n\t.reg .pred p;\n\t"                                       \
        "mbarrier.try_wait.parity.acquire.cta.shared::cta.b64 p, [%1], %2;\n\t" \
        "selp.b32 %0, 1, 0, p;\n\t}" : "=r"(_d) : "r"(_m), "r"(_p) : "memory"); \
    if (!_d) {                                                                  \
        asm volatile("{\n\t.reg .pred P1;\n\tWL_%=:\n\t"                        \
            "mbarrier.try_wait.parity.acquire.cta.shared::cta.b64 P1, [%0], %1, 0x989680;\n\t" \
            "@P1 bra.uni WD_%=;\n\tbra.uni WL_%=;\n\tWD_%=:\n\t}"               \
            :: "r"(_m), "r"(_p) : "memory");                                    \
    }                                                                           \
} while (0)
// 1D bulk TMA: global -> shared, completion via mbarrier tx-bytes
#define CP_BULK(dst, src, bytes, mbar) \
    asm volatile("cp.async.bulk.shared::cluster.global.mbarrier::complete_tx::bytes " \
                 "[%0], [%1], %2, [%3];" \
                 :: "r"(dst), "l"(src), "r"(bytes), "r"(mbar) : "memory")

// ==================== generic fp32 -> packed fp16 hi/lo ======================
// kshift = log2(K); rtshift = log2(rows per tile) (7 for A operands, 6 for W).
__global__ __launch_bounds__(256) void split_pack_k(
    const float4* __restrict__ in, __half* __restrict__ hi, __half* __restrict__ lo,
    int kshift, int rtshift, int n4)
{
    int i = blockIdx.x * 256 + threadIdx.x;
    if (i >= n4) return;
    int e   = i << 2;
    int row = e >> kshift;
    int k   = e & ((1 << kshift) - 1);
    float4 v = in[i];
    float x[4] = {v.x, v.y, v.z, v.w};
    __half h[4], l[4];
#pragma unroll
    for (int j = 0; j < 4; j++) {
        h[j] = __float2half_rn(x[j]);
        l[j] = __float2half_rn(x[j] - __half2float(h[j]));
    }
    int tile = (row >> rtshift) * (1 << (kshift - 6)) + (k >> 6);
    size_t idx = (size_t)tile * (64 << rtshift) + (row & ((1 << rtshift) - 1)) * 64
               + ((((k >> 3) ^ row) & 7) << 3) + (k & 7);
    *(uint2*)(hi + idx) = *(uint2*)h;
    *(uint2*)(lo + idx) = *(uint2*)l;
}

// ==================== split-fp16 HMMA NT GEMM (bulk-TMA staged) ==============
// C[m,n] = sum_k A[m,k]*W[n,k];  D = AH*WH + AH*WL + AL*WH  (drops AL*WL)
// Tile 128m x 64n, BK=64. 2-stage TMA pipeline, 48KB/stage, 96KB smem total
// -> 2 CTAs/SM (cross-CTA latency hiding). 8 warps (2m x 4n), warp tile 64x16.
// EPI: 0=none, 1=softplus(v+bias[n]).
template<int EPI>
__global__ __launch_bounds__(256, 2) void hmma_gemm(
    const __half* __restrict__ Ahi, const __half* __restrict__ Alo,
    const __half* __restrict__ Whi, const __half* __restrict__ Wlo,
    const float* __restrict__ bias, float* __restrict__ C,
    int N, int K)
{
    extern __shared__ __align__(128) char smem[];
    __shared__ __align__(8) uint64_t mbars[2];
    const uint32_t sb = smem_u32(smem);
    const int tid  = threadIdx.x;
    const int warp = tid >> 5, lane = tid & 31;
    const int wm = warp >> 2, wn = warp & 3;     // 2m x 4n warp grid
    const int bm = blockIdx.y * 128, bn = blockIdx.x * 64;
    const int iters = K >> 6;

    const uint32_t mb0 = smem_u32(&mbars[0]);
    const uint32_t mb1 = smem_u32(&mbars[1]);
    if (tid == 0) { MBAR_INIT(mb0, 1); MBAR_INIT(mb1, 1); }
    __syncthreads();

    // packed tile bases: A tiles 16KB (128 rows), W tiles 8KB (64 rows)
    const char* srcA_hi = (const char*)Ahi + (size_t)(bm >> 7) * iters * 16384;
    const char* srcA_lo = (const char*)Alo + (size_t)(bm >> 7) * iters * 16384;
    const char* srcW_hi = (const char*)Whi + (size_t)(bn >> 6) * iters * 8192;
    const char* srcW_lo = (const char*)Wlo + (size_t)(bn >> 6) * iters * 8192;

    // stage layout: AH@0(16K) AL@16K(16K) WH@32K(8K) WL@40K(8K); stride 48K
    if (tid == 0) {
#pragma unroll
        for (int s = 0; s < 2; s++) {
            uint32_t mb = s ? mb1 : mb0;
            MBAR_EXPECT_TX(mb, 49152u);
            uint32_t d = sb + (uint32_t)s * 49152u;
            CP_BULK(d,         srcA_hi + (size_t)s * 16384, 16384u, mb);
            CP_BULK(d + 16384, srcA_lo + (size_t)s * 16384, 16384u, mb);
            CP_BULK(d + 32768, srcW_hi + (size_t)s * 8192,  8192u,  mb);
            CP_BULK(d + 40960, srcW_lo + (size_t)s * 8192,  8192u,  mb);
        }
    }

    // ldmatrix lane address components
    const int arow = wm * 64 + (lane & 7) + ((lane >> 3) & 1) * 8;  // + mt*16
    const int ach  = lane >> 4;
    const int brow = wn * 16 + (lane & 7) + ((lane >> 4) & 1) * 8;
    const int bch  = (lane >> 3) & 1;
    const int xr   = lane & 7;

    float acc[4][2][4];
#pragma unroll
    for (int mt = 0; mt < 4; mt++)
#pragma unroll
        for (int nt = 0; nt < 2; nt++)
#pragma unroll
            for (int q = 0; q < 4; q++) acc[mt][nt][q] = 0.f;

    int ph0 = 0, ph1 = 0;
    for (int it = 0; it < iters; it++) {
        const int st = it & 1;
        if (st == 0) { MBAR_WAIT(mb0, ph0); ph0 ^= 1; }
        else         { MBAR_WAIT(mb1, ph1); ph1 ^= 1; }

        const uint32_t so = (uint32_t)st * 49152u;
#pragma unroll
        for (int ks = 0; ks < 4; ks++) {
            uint32_t ah[4][4], al[4][4], bh[4], bl[4];
#pragma unroll
            for (int mt = 0; mt < 4; mt++) {
                uint32_t off = so + (uint32_t)(arow + mt * 16) * 128
                             + ((uint32_t)(((ks << 1) + ach) ^ xr) << 4);
                ldsm_x4(ah[mt], sb + off);
                ldsm_x4(al[mt], sb + 16384 + off);
            }
            {
                uint32_t off = so + 32768 + (uint32_t)brow * 128
                             + ((uint32_t)(((ks << 1) + bch) ^ xr) << 4);
                ldsm_x4(bh, sb + off);
                ldsm_x4(bl, sb + 8192 + off);
            }
#pragma unroll
            for (int mt = 0; mt < 4; mt++)
#pragma unroll
                for (int t2 = 0; t2 < 2; t2++) {
                    mma16816(acc[mt][t2], ah[mt], &bh[t2 * 2]);
                    mma16816(acc[mt][t2], ah[mt], &bl[t2 * 2]);
                    mma16816(acc[mt][t2], al[mt], &bh[t2 * 2]);
                }
        }
        __syncthreads();   // all warps done reading stage st
        if (tid == 0 && it + 2 < iters) {
            uint32_t mb = st ? mb1 : mb0;
            MBAR_EXPECT_TX(mb, 49152u);
            uint32_t d = sb + so;
            size_t o16 = (size_t)(it + 2) * 16384;
            size_t o8  = (size_t)(it + 2) * 8192;
            CP_BULK(d,         srcA_hi + o16, 16384u, mb);
            CP_BULK(d + 16384, srcA_lo + o16, 16384u, mb);
            CP_BULK(d + 32768, srcW_hi + o8,  8192u,  mb);
            CP_BULK(d + 40960, srcW_lo + o8,  8192u,  mb);
        }
    }

    // ---- epilogue: fragment -> global (optionally bias + softplus) ----
    const int r0   = bm + wm * 64 + (lane >> 2);
    const int col0 = bn + wn * 16 + (lane & 3) * 2;
#pragma unroll
    for (int mt = 0; mt < 4; mt++) {
#pragma unroll
        for (int nt = 0; nt < 2; nt++) {
            int row = r0 + mt * 16;
            int col = col0 + nt * 8;
            float v[4] = {acc[mt][nt][0], acc[mt][nt][1],
                          acc[mt][nt][2], acc[mt][nt][3]};
            if (EPI == 1) {
                float b0 = bias[col], b1 = bias[col + 1];
                v[0] += b0; v[1] += b1; v[2] += b0; v[3] += b1;
#pragma unroll
                for (int q = 0; q < 4; q++)
                    v[q] = (v[q] > 20.f) ? v[q] : log1pf(__expf(v[q]));
            }
            *(float2*)(C + (size_t)row * N + col)       = make_float2(v[0], v[1]);
            *(float2*)(C + (size_t)(row + 8) * N + col) = make_float2(v[2], v[3]);
        }
    }
}

// ---------- depthwise causal conv (taps=4) + SiLU + fused hi/lo pack ---------
// 4 consecutive channels per thread; writes fp32 xi AND packed hi/lo (K=DI, RT=128).
__global__ __launch_bounds__(256) void conv_silu_pack_k(
    const float* __restrict__ xz, const float4* __restrict__ cw,
    const float* __restrict__ cb, float* __restrict__ xi,
    __half* __restrict__ hi, __half* __restrict__ lo)
{
    int i = blockIdx.x * 256 + threadIdx.x;   // over NT*DI/4
    int e = i << 2;
    int c = e & (DI - 1);
    int t = e >> 11;
    int l = t & (LLEN - 1);
    const float* base = xz + (size_t)(t - l) * (2 * DI) + c;
    float4 w0 = cw[c], w1 = cw[c + 1], w2 = cw[c + 2], w3 = cw[c + 3];
    float4 bz = *(const float4*)(cb + c);
    float acc[4] = {bz.x, bz.y, bz.z, bz.w};
#pragma unroll
    for (int j = 0; j < 4; j++) {
        int ll = l - 3 + j;
        if (ll >= 0) {
            float4 v = *(const float4*)(base + (size_t)ll * (2 * DI));
            acc[0] = fmaf(((const float*)&w0)[j], v.x, acc[0]);
            acc[1] = fmaf(((const float*)&w1)[j], v.y, acc[1]);
            acc[2] = fmaf(((const float*)&w2)[j], v.z, acc[2]);
            acc[3] = fmaf(((const float*)&w3)[j], v.w, acc[3]);
        }
    }
    __half h[4], lw[4];
#pragma unroll
    for (int q = 0; q < 4; q++) {
        acc[q] = acc[q] / (1.f + __expf(-acc[q]));   // silu
        h[q]  = __float2half_rn(acc[q]);
        lw[q] = __float2half_rn(acc[q] - __half2float(h[q]));
    }
    *(float4*)(xi + e) = make_float4(acc[0], acc[1], acc[2], acc[3]);
    int tile = (t >> 7) * 32 + (c >> 6);
    size_t idx = (size_t)tile * 8192 + (t & 127) * 64
               + ((((c >> 3) ^ t) & 7) << 3) + (c & 7);
    *(uint2*)(hi + idx) = *(uint2*)h;
    *(uint2*)(lo + idx) = *(uint2*)lw;
}

// ---------------- x_proj GEMM (N=32): bc[t, 0..31] ---------------------------
__global__ __launch_bounds__(256) void bc_k(const float* __restrict__ xi,
                                            const float* __restrict__ xw,
                                            float* __restrict__ bc)
{
    __shared__ float ws[32][257];
    __shared__ float xs[8][257];
    int tid = threadIdx.x, warp = tid >> 5, lane = tid & 31;
    int tok0 = blockIdx.x * 8;
    float acc = 0.f;
    for (int kc = 0; kc < DI; kc += 256) {
#pragma unroll
        for (int i = 0; i < 32; i++)
            ws[i][tid] = xw[i * DI + kc + tid];
#pragma unroll
        for (int i = 0; i < 8; i++)
            xs[i][tid] = xi[(tok0 + i) * DI + kc + tid];
        __syncthreads();
#pragma unroll 8
        for (int k = 0; k < 256; k++)
            acc = fmaf(xs[warp][k], ws[lane][k], acc);
        __syncthreads();
    }
    bc[(tok0 + warp) * (2 * DS) + lane] = acc;
}

// ---------------- selective scan + fused output gating -----------------------
__global__ __launch_bounds__(256) void scan_k(
    const float* __restrict__ delta, const float* __restrict__ bc,
    const float* __restrict__ xi,    const float* __restrict__ xz,
    const float* __restrict__ A_log, const float* __restrict__ Dp,
    float* __restrict__ fin)
{
    int g = blockIdx.x * 16 + (threadIdx.x >> 4);
    int s = threadIdx.x & 15;
    int b = g >> 11;
    int d = g & (DI - 1);

    float As = -expf(A_log[d * DS + s]);
    float Dd = Dp[d];

    int base_d  = (b * LLEN) * DI + d;
    int base_bc = (b * LLEN) * (2 * DS);
    int base_z  = (b * LLEN) * (2 * DI) + DI + d;

    float h = 0.f;
    for (int l = 0; l < LLEN; l++) {
        float dl = delta[base_d];
        float xv = xi[base_d];
        float Bt = bc[base_bc + s];
        float Ct = bc[base_bc + DS + s];
        float ab = __expf(dl * As);
        h = fmaf(ab, h, dl * Bt * xv);
        float y = h * Ct;
        y += __shfl_xor_sync(0xffffffffu, y, 1);
        y += __shfl_xor_sync(0xffffffffu, y, 2);
        y += __shfl_xor_sync(0xffffffffu, y, 4);
        y += __shfl_xor_sync(0xffffffffu, y, 8);
        if (s == 0) {
            float zv  = xz[base_z];
            float sig = 1.f / (1.f + __expf(-zv));
            fin[base_d] = (y + xv * Dd) * (zv * sig);
        }
        base_d  += DI;
        base_bc += 2 * DS;
        base_z  += 2 * DI;
    }
}

// ---------------- launch ------------------------------------------------------
extern "C" void kernel_launch(void* const* d_in, const int* in_sizes, int n_in,
                              void* d_out, int out_size)
{
    const float* x          = (const float*)d_in[0];
    const float* in_proj_w  = (const float*)d_in[1];
    const float* conv_w     = (const float*)d_in[2];
    const float* conv_b     = (const float*)d_in[3];
    const float* x_proj_w   = (const float*)d_in[4];
    const float* dt_proj_w  = (const float*)d_in[5];
    const float* dt_proj_b  = (const float*)d_in[6];
    const float* A_log      = (const float*)d_in[7];
    const float* Dvec       = (const float*)d_in[8];
    const float* out_proj_w = (const float*)d_in[9];

    float *xz, *xi, *delta, *bcv, *fin;
    __half *ahi, *alo, *whi, *wlo;
    cudaGetSymbolAddress((void**)&xz,    g_xz);
    cudaGetSymbolAddress((void**)&xi,    g_xi);
    cudaGetSymbolAddress((void**)&delta, g_delta);
    cudaGetSymbolAddress((void**)&bcv,   g_bc);
    cudaGetSymbolAddress((void**)&fin,   g_fin);
    cudaGetSymbolAddress((void**)&ahi,   g_ahi);
    cudaGetSymbolAddress((void**)&alo,   g_alo);
    cudaGetSymbolAddress((void**)&whi,   g_whi);
    cudaGetSymbolAddress((void**)&wlo,   g_wlo);

    const int SMEM_SZ = 2 * 49152;   // 96 KB: 2 stages x 48KB -> 2 CTAs/SM
    cudaFuncSetAttribute(hmma_gemm<0>, cudaFuncAttributeMaxDynamicSharedMemorySize, SMEM_SZ);
    cudaFuncSetAttribute(hmma_gemm<1>, cudaFuncAttributeMaxDynamicSharedMemorySize, SMEM_SZ);

    // 1) in_proj: x[8192,1024] @ W[4096,1024]^T -> xz
    split_pack_k<<<(NT * DM / 4 + 255) / 256, 256>>>((const float4*)x, ahi, alo, 10, 7, NT * DM / 4);
    split_pack_k<<<(4096 * 1024 / 4 + 255) / 256, 256>>>((const float4*)in_proj_w, whi, wlo, 10, 6, 4096 * 1024 / 4);
    hmma_gemm<0><<<dim3(4096 / 64, NT / 128), 256, SMEM_SZ>>>(
        ahi, alo, whi, wlo, nullptr, xz, 4096, DM);

    // 2) causal depthwise conv + silu -> xi (fp32) + packed hi/lo (for dt GEMM)
    conv_silu_pack_k<<<(NT * DI / 4) / 256, 256>>>(
        xz, (const float4*)conv_w, conv_b, xi, ahi, alo);

    // 3) dt_proj + bias + softplus -> delta
    split_pack_k<<<(DI * DI / 4 + 255) / 256, 256>>>((const float4*)dt_proj_w, whi, wlo, 11, 6, DI * DI / 4);
    hmma_gemm<1><<<dim3(DI / 64, NT / 128), 256, SMEM_SZ>>>(
        ahi, alo, whi, wlo, dt_proj_b, delta, DI, DI);

    // 4) x_proj -> bc (fp32, small N)
    bc_k<<<NT / 8, 256>>>(xi, x_proj_w, bcv);

    // 5) selective scan + (y + xi*D) * silu(z) -> fin
    scan_k<<<(NB * DI) / 16, 256>>>(delta, bcv, xi, xz, A_log, Dvec, fin);

    // 6) out_proj: fin[8192,2048] @ W[1024,2048]^T -> out
    split_pack_k<<<(NT * DI / 4 + 255) / 256, 256>>>((const float4*)fin, ahi, alo, 11, 7, NT * DI / 4);
    split_pack_k<<<(DM * DI / 4 + 255) / 256, 256>>>((const float4*)out_proj_w, whi, wlo, 11, 6, DM * DI / 4);
    hmma_gemm<0><<<dim3(DM / 64, NT / 128), 256, SMEM_SZ>>>(
        ahi, alo, whi, wlo, nullptr, (float*)d_out, DM, DI);
}